// round 5
// baseline (speedup 1.0000x reference)
#include <cuda_runtime.h>

// Plenoxel forward: R=4096 rays, S=128 samples/ray, 160^3 grid.
// d_in[0] ray_origins float32[R,3], d_in[1] ray_directions float32[R,3],
// d_in[2] density float32[160^3], d_in[3] sh_coeffs float32[160^3,3,9]
// out: concat(rgb[R,3], depth[R], acc[R])

#define GRES        160
#define NSAMP       128
#define T_NEAR      0.1f
#define T_FAR       10.0f
#define FULLMASK    0xffffffffu

// Accumulate wgt * (SH_row(idx) . basis) into 3 channels, branch-free,
// with a ROLLING chunk window to keep live registers low:
//   d0 consumes chunks 0..2, d1 chunks 2..5, d2 chunks 4..7.
// Basis is shifted by O into a 12-slot zero-padded vector (bs), so the data
// chunks are consumed at fixed indices. bs[k] = b[k-O] (0 outside [0,9)).
__device__ __forceinline__ void sh_row_accum(const float4* __restrict__ sh4, int idx,
                                             const float (&b)[9], float wgt,
                                             float& c0, float& c1, float& c2)
{
    const int F    = idx * 27;
    const int base = F >> 2;
    const int O    = F & 3;
    const bool s2  = (O & 2) != 0;
    const bool s1  = (O & 1) != 0;

    // two-stage shifted basis (≈23 SELs)
    float t[12];
    t[0]  = s2 ? 0.f  : b[0];
    t[1]  = s2 ? 0.f  : b[1];
    #pragma unroll
    for (int k = 2; k <= 8; k++) t[k] = s2 ? b[k-2] : b[k];
    t[9]  = s2 ? b[7] : 0.f;
    t[10] = s2 ? b[8] : 0.f;
    t[11] = 0.f;

    float bs[12];
    bs[0] = s1 ? 0.f : t[0];
    #pragma unroll
    for (int k = 1; k < 12; k++) bs[k] = s1 ? t[k-1] : t[k];

    const float4* p = sh4 + base;

    // --- d0: v[0..11] = chunks 0..2 ---
    float4 q0 = __ldg(p + 0);
    float4 q1 = __ldg(p + 1);
    float4 q2 = __ldg(p + 2);
    float4 q3 = __ldg(p + 3);      // prefetch for d1

    float d0 = 0.f;
    d0 = fmaf(q0.x, bs[0],  d0); d0 = fmaf(q0.y, bs[1],  d0);
    d0 = fmaf(q0.z, bs[2],  d0); d0 = fmaf(q0.w, bs[3],  d0);
    d0 = fmaf(q1.x, bs[4],  d0); d0 = fmaf(q1.y, bs[5],  d0);
    d0 = fmaf(q1.z, bs[6],  d0); d0 = fmaf(q1.w, bs[7],  d0);
    d0 = fmaf(q2.x, bs[8],  d0); d0 = fmaf(q2.y, bs[9],  d0);
    d0 = fmaf(q2.z, bs[10], d0); d0 = fmaf(q2.w, bs[11], d0);

    // --- d1: v[9..20] = q2.yzw, q3, q4, q5.x ---
    float4 q4 = __ldg(p + 4);
    float4 q5 = __ldg(p + 5);

    float d1 = 0.f;
    d1 = fmaf(q2.y, bs[0],  d1); d1 = fmaf(q2.z, bs[1],  d1);
    d1 = fmaf(q2.w, bs[2],  d1);
    d1 = fmaf(q3.x, bs[3],  d1); d1 = fmaf(q3.y, bs[4],  d1);
    d1 = fmaf(q3.z, bs[5],  d1); d1 = fmaf(q3.w, bs[6],  d1);
    d1 = fmaf(q4.x, bs[7],  d1); d1 = fmaf(q4.y, bs[8],  d1);
    d1 = fmaf(q4.z, bs[9],  d1); d1 = fmaf(q4.w, bs[10], d1);
    d1 = fmaf(q5.x, bs[11], d1);

    // --- d2: v[18..29] = q4.zw, q5, q6, q7.xy ---
    float4 q6 = __ldg(p + 6);
    float4 q7 = make_float4(0.f, 0.f, 0.f, 0.f);
    if (s2) q7 = __ldg(p + 7);     // only needed (and in-bounds-required) when O>=2

    float d2 = 0.f;
    d2 = fmaf(q4.z, bs[0],  d2); d2 = fmaf(q4.w, bs[1],  d2);
    d2 = fmaf(q5.x, bs[2],  d2); d2 = fmaf(q5.y, bs[3],  d2);
    d2 = fmaf(q5.z, bs[4],  d2); d2 = fmaf(q5.w, bs[5],  d2);
    d2 = fmaf(q6.x, bs[6],  d2); d2 = fmaf(q6.y, bs[7],  d2);
    d2 = fmaf(q6.z, bs[8],  d2); d2 = fmaf(q6.w, bs[9],  d2);
    d2 = fmaf(q7.x, bs[10], d2); d2 = fmaf(q7.y, bs[11], d2);

    c0 = fmaf(wgt, d0, c0);
    c1 = fmaf(wgt, d1, c1);
    c2 = fmaf(wgt, d2, c2);
}

__global__ __launch_bounds__(256, 5) void plenoxel_fwd_kernel(
    const float* __restrict__ ro,
    const float* __restrict__ rd,
    const float* __restrict__ density,
    const float* __restrict__ sh,
    float* __restrict__ out,
    int R)
{
    const float4* __restrict__ sh4 = (const float4*)sh;

    const int warp = threadIdx.x >> 5;      // 0..7
    const int lane = threadIdx.x & 31;
    const int rib  = warp >> 2;              // ray-in-block 0..1
    const int wir  = warp & 3;               // warp-in-ray  0..3
    const int r    = min(blockIdx.x * 2 + rib, R - 1);

    __shared__ float sProd[2][4];
    __shared__ float sPart[2][4][5];

    const float ox = ro[r*3+0], oy = ro[r*3+1], oz = ro[r*3+2];
    const float dx = rd[r*3+0], dy = rd[r*3+1], dz = rd[r*3+2];

    const float dnorm = sqrtf(dx*dx + dy*dy + dz*dz);
    const float inv   = 1.0f / (dnorm + 1e-8f);
    const float nx = dx*inv, ny = dy*inv, nz = dz*inv;

    float b[9];
    b[0] =  0.28209479177387814f;
    b[1] = -0.48860251190291987f * ny;
    b[2] =  0.48860251190291987f * nz;
    b[3] = -0.48860251190291987f * nx;
    b[4] =  1.0925484305920792f  * nx * ny;
    b[5] = -1.0925484305920792f  * ny * nz;
    b[6] =  0.31539156525252005f * (2.0f*nz*nz - nx*nx - ny*ny);
    b[7] = -1.0925484305920792f  * nx * nz;
    b[8] =  0.5462742152960396f  * (nx*nx - ny*ny);

    const float dt = (T_FAR - T_NEAR) / (float)(NSAMP - 1);

    // --- one sample per lane ---
    const int   s = wir * 32 + lane;
    const float t = T_NEAR + dt * (float)s;

    float vx = (ox + t*dx + 1.0f) * 80.0f;
    float vy = (oy + t*dy + 1.0f) * 80.0f;
    float vz = (oz + t*dz + 1.0f) * 80.0f;
    vx = fminf(fmaxf(vx, 0.0f), 159.0f);
    vy = fminf(fmaxf(vy, 0.0f), 159.0f);
    vz = fminf(fmaxf(vz, 0.0f), 159.0f);

    const float fx = floorf(vx), fy = floorf(vy), fz = floorf(vz);
    const int x0 = (int)fx, y0 = (int)fy, z0 = (int)fz;
    const int x1 = min(x0 + 1, GRES - 1);
    const int y1 = min(y0 + 1, GRES - 1);
    const int z1 = min(z0 + 1, GRES - 1);
    const float ddx = vx - fx, ddy = vy - fy, ddz = vz - fz;
    const float wx0 = 1.0f - ddx, wx1 = ddx;
    const int   xd  = x1 - x0;

    float dens = 0.0f, c0 = 0.0f, c1 = 0.0f, c2 = 0.0f;

    #pragma unroll 1
    for (int cz = 0; cz < 2; cz++) {
        const int   zi = cz ? z1 : z0;
        const float wz = cz ? ddz : (1.0f - ddz);
        #pragma unroll 1
        for (int cy = 0; cy < 2; cy++) {
            const int   yi  = cy ? y1 : y0;
            const float wy  = cy ? ddy : (1.0f - ddy);
            const float wyz = wz * wy;
            const int idx0 = (zi * GRES + yi) * GRES + x0;
            const int idx1 = idx0 + xd;

            dens = fmaf(wyz,
                        fmaf(wx0, __ldg(density + idx0), wx1 * __ldg(density + idx1)),
                        dens);
            sh_row_accum(sh4, idx0, b, wyz * wx0, c0, c1, c2);
            sh_row_accum(sh4, idx1, b, wyz * wx1, c0, c1, c2);
        }
    }

    // colors (fast-math transcendentals; error ~2^-21 << 1e-3 tolerance)
    const float col0 = __fdividef(1.0f, 1.0f + __expf(-c0));
    const float col1 = __fdividef(1.0f, 1.0f + __expf(-c1));
    const float col2 = __fdividef(1.0f, 1.0f + __expf(-c2));

    const float dist  = ((s == NSAMP - 1) ? 1e10f : dt) * dnorm;
    const float alpha = 1.0f - __expf(-fmaxf(dens, 0.0f) * dist);

    // warp-local exclusive cumprod of (1 - alpha + 1e-10)
    float incl = 1.0f - alpha + 1e-10f;
    #pragma unroll
    for (int o = 1; o < 32; o <<= 1) {
        const float pv = __shfl_up_sync(FULLMASK, incl, o);
        if (lane >= o) incl *= pv;
    }
    float excl = __shfl_up_sync(FULLMASK, incl, 1);
    if (lane == 0) excl = 1.0f;
    const float warpProd = __shfl_sync(FULLMASK, incl, 31);

    const float w = alpha * excl;
    float rgb0 = w * col0;
    float rgb1 = w * col1;
    float rgb2 = w * col2;
    float dep  = w * t;
    float acc  = w;

    #pragma unroll
    for (int o = 16; o > 0; o >>= 1) {
        rgb0 += __shfl_xor_sync(FULLMASK, rgb0, o);
        rgb1 += __shfl_xor_sync(FULLMASK, rgb1, o);
        rgb2 += __shfl_xor_sync(FULLMASK, rgb2, o);
        dep  += __shfl_xor_sync(FULLMASK, dep,  o);
        acc  += __shfl_xor_sync(FULLMASK, acc,  o);
    }

    if (lane == 0) {
        sPart[rib][wir][0] = rgb0;
        sPart[rib][wir][1] = rgb1;
        sPart[rib][wir][2] = rgb2;
        sPart[rib][wir][3] = dep;
        sPart[rib][wir][4] = acc;
        sProd[rib][wir]    = warpProd;
    }
    __syncthreads();

    // one thread per ray composes the 4 warp segments
    if (wir == 0 && lane == 0) {
        float P = 1.0f;
        float o0 = 0.f, o1 = 0.f, o2 = 0.f, od = 0.f, oa = 0.f;
        #pragma unroll
        for (int ws = 0; ws < 4; ws++) {
            o0 += P * sPart[rib][ws][0];
            o1 += P * sPart[rib][ws][1];
            o2 += P * sPart[rib][ws][2];
            od += P * sPart[rib][ws][3];
            oa += P * sPart[rib][ws][4];
            P  *= sProd[rib][ws];
        }
        out[r*3 + 0] = o0;
        out[r*3 + 1] = o1;
        out[r*3 + 2] = o2;
        out[R*3 + r] = od;
        out[R*4 + r] = oa;
    }
}

extern "C" void kernel_launch(void* const* d_in, const int* in_sizes, int n_in,
                              void* d_out, int out_size)
{
    const float* ro      = (const float*)d_in[0];
    const float* rd      = (const float*)d_in[1];
    const float* density = (const float*)d_in[2];
    const float* sh      = (const float*)d_in[3];
    float* out           = (float*)d_out;

    const int R = in_sizes[0] / 3;      // 4096
    const int blocks = (R + 1) / 2;     // 2 rays (8 warps) per 256-thread block

    plenoxel_fwd_kernel<<<blocks, 256>>>(ro, rd, density, sh, out, R);
}

// round 6
// speedup vs baseline: 1.7353x; 1.7353x over previous
#include <cuda_runtime.h>

// Plenoxel forward: R=4096 rays, S=128 samples/ray, 160^3 grid.
// d_in[0] ray_origins float32[R,3], d_in[1] ray_directions float32[R,3],
// d_in[2] density float32[160^3], d_in[3] sh_coeffs float32[160^3,3,9]
// out: concat(rgb[R,3], depth[R], acc[R])

#define GRES        160
#define NSAMP       128
#define T_NEAR      0.1f
#define T_FAR       10.0f
#define FULLMASK    0xffffffffu

// R4-style: batched 8-chunk window (max MLP) + shifted-basis (23 SELs).
__device__ __forceinline__ void sh_row_accum(const float4* __restrict__ sh4, int idx,
                                             const float (&b)[9], float wgt,
                                             float& c0, float& c1, float& c2)
{
    const int F    = idx * 27;
    const int base = F >> 2;
    const int O    = F & 3;
    const bool s2  = (O & 2) != 0;
    const bool s1  = (O & 1) != 0;

    float v[32];
    #pragma unroll
    for (int i = 0; i < 7; i++) {
        const float4 q = __ldg(sh4 + base + i);
        v[4*i+0] = q.x; v[4*i+1] = q.y; v[4*i+2] = q.z; v[4*i+3] = q.w;
    }
    {   // 8th chunk only needed (and only in-bounds-required) when O>=2
        float4 q = make_float4(0.f, 0.f, 0.f, 0.f);
        if (s2) q = __ldg(sh4 + base + 7);
        v[28] = q.x; v[29] = q.y; v[30] = q.z; v[31] = q.w;
    }

    // bshift[k] = (0 <= k-O < 9) ? b[k-O] : 0
    float t[12];
    t[0]  = s2 ? 0.f  : b[0];
    t[1]  = s2 ? 0.f  : b[1];
    #pragma unroll
    for (int k = 2; k <= 8; k++) t[k] = s2 ? b[k-2] : b[k];
    t[9]  = s2 ? b[7] : 0.f;
    t[10] = s2 ? b[8] : 0.f;
    t[11] = 0.f;

    float bs[12];
    bs[0] = s1 ? 0.f : t[0];
    #pragma unroll
    for (int k = 1; k < 12; k++) bs[k] = s1 ? t[k-1] : t[k];

    float d0 = 0.f, d1 = 0.f, d2 = 0.f;
    #pragma unroll
    for (int k = 0; k < 12; k++) {
        const float bk = bs[k];
        d0 = fmaf(v[k],      bk, d0);
        d1 = fmaf(v[9 + k],  bk, d1);
        d2 = fmaf(v[18 + k], bk, d2);
    }
    c0 = fmaf(wgt, d0, c0);
    c1 = fmaf(wgt, d1, c1);
    c2 = fmaf(wgt, d2, c2);
}

__global__ __launch_bounds__(256) void plenoxel_fwd_kernel(
    const float* __restrict__ ro,
    const float* __restrict__ rd,
    const float* __restrict__ density,
    const float* __restrict__ sh,
    float* __restrict__ out,
    int R)
{
    const float4* __restrict__ sh4 = (const float4*)sh;

    const int warp = threadIdx.x >> 5;      // 0..7
    const int lane = threadIdx.x & 31;
    const int rib  = warp >> 2;              // ray-in-block 0..1
    const int wir  = warp & 3;               // warp-in-ray  0..3
    const int r    = min(blockIdx.x * 2 + rib, R - 1);

    __shared__ float sProd[2][4];
    __shared__ float sPart[2][4][5];

    const float ox = ro[r*3+0], oy = ro[r*3+1], oz = ro[r*3+2];
    const float dx = rd[r*3+0], dy = rd[r*3+1], dz = rd[r*3+2];

    const float dnorm = sqrtf(dx*dx + dy*dy + dz*dz);
    const float inv   = 1.0f / (dnorm + 1e-8f);
    const float nx = dx*inv, ny = dy*inv, nz = dz*inv;

    float b[9];
    b[0] =  0.28209479177387814f;
    b[1] = -0.48860251190291987f * ny;
    b[2] =  0.48860251190291987f * nz;
    b[3] = -0.48860251190291987f * nx;
    b[4] =  1.0925484305920792f  * nx * ny;
    b[5] = -1.0925484305920792f  * ny * nz;
    b[6] =  0.31539156525252005f * (2.0f*nz*nz - nx*nx - ny*ny);
    b[7] = -1.0925484305920792f  * nx * nz;
    b[8] =  0.5462742152960396f  * (nx*nx - ny*ny);

    const float dt = (T_FAR - T_NEAR) / (float)(NSAMP - 1);

    // --- one sample per lane ---
    const int   s = wir * 32 + lane;
    const float t = T_NEAR + dt * (float)s;

    float vx = (ox + t*dx + 1.0f) * 80.0f;
    float vy = (oy + t*dy + 1.0f) * 80.0f;
    float vz = (oz + t*dz + 1.0f) * 80.0f;
    vx = fminf(fmaxf(vx, 0.0f), 159.0f);
    vy = fminf(fmaxf(vy, 0.0f), 159.0f);
    vz = fminf(fmaxf(vz, 0.0f), 159.0f);

    const float fx = floorf(vx), fy = floorf(vy), fz = floorf(vz);
    const int x0 = (int)fx, y0 = (int)fy, z0 = (int)fz;
    const int x1 = min(x0 + 1, GRES - 1);
    const int y1 = min(y0 + 1, GRES - 1);
    const int z1 = min(z0 + 1, GRES - 1);
    const float ddx = vx - fx, ddy = vy - fy, ddz = vz - fz;
    const float wx0 = 1.0f - ddx, wx1 = ddx;
    const int   xd  = x1 - x0;

    // ---- Phase 1: density only (cheap), alpha, transmittance scan ----
    float dens = 0.0f;
    {
        const int  rz0 = z0 * GRES, rz1 = z1 * GRES;
        const int  i00 = (rz0 + y0) * GRES + x0;
        const int  i01 = (rz0 + y1) * GRES + x0;
        const int  i10 = (rz1 + y0) * GRES + x0;
        const int  i11 = (rz1 + y1) * GRES + x0;
        const float wz0 = 1.0f - ddz, wz1 = ddz;
        const float wy0 = 1.0f - ddy, wy1 = ddy;

        const float d000 = __ldg(density + i00),      d001 = __ldg(density + i00 + xd);
        const float d010 = __ldg(density + i01),      d011 = __ldg(density + i01 + xd);
        const float d100 = __ldg(density + i10),      d101 = __ldg(density + i10 + xd);
        const float d110 = __ldg(density + i11),      d111 = __ldg(density + i11 + xd);

        dens = wz0 * (wy0 * (wx0*d000 + wx1*d001) + wy1 * (wx0*d010 + wx1*d011))
             + wz1 * (wy0 * (wx0*d100 + wx1*d101) + wy1 * (wx0*d110 + wx1*d111));
    }

    const float dist  = ((s == NSAMP - 1) ? 1e10f : dt) * dnorm;
    const float alpha = 1.0f - __expf(-fmaxf(dens, 0.0f) * dist);

    // warp-local exclusive cumprod of (1 - alpha + 1e-10)
    float incl = 1.0f - alpha + 1e-10f;
    #pragma unroll
    for (int o = 1; o < 32; o <<= 1) {
        const float pv = __shfl_up_sync(FULLMASK, incl, o);
        if (lane >= o) incl *= pv;
    }
    float excl = __shfl_up_sync(FULLMASK, incl, 1);
    if (lane == 0) excl = 1.0f;
    const float warpProd = __shfl_sync(FULLMASK, incl, 31);

    const float w = alpha * excl;   // warp-local weight (global scale applied at compose)

    // ---- Phase 2: SH gather + shade, ONLY for lanes with nonzero weight ----
    // alpha==0 exactly when dens<=0 (expf(0)==1), so skipped lanes contribute
    // exactly 0 to rgb/depth/acc regardless of color. Predicated-off lanes
    // issue no L1 wavefronts for the 60 LDG.128s below (~50% of samples).
    float col0 = 0.f, col1 = 0.f, col2 = 0.f;
    if (w != 0.0f) {
        float c0 = 0.0f, c1 = 0.0f, c2 = 0.0f;
        #pragma unroll 1
        for (int cz = 0; cz < 2; cz++) {
            const int   zi = cz ? z1 : z0;
            const float wz = cz ? ddz : (1.0f - ddz);
            #pragma unroll 1
            for (int cy = 0; cy < 2; cy++) {
                const int   yi  = cy ? y1 : y0;
                const float wy  = cy ? ddy : (1.0f - ddy);
                const float wyz = wz * wy;
                const int idx0 = (zi * GRES + yi) * GRES + x0;

                sh_row_accum(sh4, idx0,      b, wyz * wx0, c0, c1, c2);
                sh_row_accum(sh4, idx0 + xd, b, wyz * wx1, c0, c1, c2);
            }
        }
        col0 = __fdividef(1.0f, 1.0f + __expf(-c0));
        col1 = __fdividef(1.0f, 1.0f + __expf(-c1));
        col2 = __fdividef(1.0f, 1.0f + __expf(-c2));
    }

    float rgb0 = w * col0;
    float rgb1 = w * col1;
    float rgb2 = w * col2;
    float dep  = w * t;
    float acc  = w;

    #pragma unroll
    for (int o = 16; o > 0; o >>= 1) {
        rgb0 += __shfl_xor_sync(FULLMASK, rgb0, o);
        rgb1 += __shfl_xor_sync(FULLMASK, rgb1, o);
        rgb2 += __shfl_xor_sync(FULLMASK, rgb2, o);
        dep  += __shfl_xor_sync(FULLMASK, dep,  o);
        acc  += __shfl_xor_sync(FULLMASK, acc,  o);
    }

    if (lane == 0) {
        sPart[rib][wir][0] = rgb0;
        sPart[rib][wir][1] = rgb1;
        sPart[rib][wir][2] = rgb2;
        sPart[rib][wir][3] = dep;
        sPart[rib][wir][4] = acc;
        sProd[rib][wir]    = warpProd;
    }
    __syncthreads();

    // one thread per ray composes the 4 warp segments
    if (wir == 0 && lane == 0) {
        float P = 1.0f;
        float o0 = 0.f, o1 = 0.f, o2 = 0.f, od = 0.f, oa = 0.f;
        #pragma unroll
        for (int ws = 0; ws < 4; ws++) {
            o0 += P * sPart[rib][ws][0];
            o1 += P * sPart[rib][ws][1];
            o2 += P * sPart[rib][ws][2];
            od += P * sPart[rib][ws][3];
            oa += P * sPart[rib][ws][4];
            P  *= sProd[rib][ws];
        }
        out[r*3 + 0] = o0;
        out[r*3 + 1] = o1;
        out[r*3 + 2] = o2;
        out[R*3 + r] = od;
        out[R*4 + r] = oa;
    }
}

extern "C" void kernel_launch(void* const* d_in, const int* in_sizes, int n_in,
                              void* d_out, int out_size)
{
    const float* ro      = (const float*)d_in[0];
    const float* rd      = (const float*)d_in[1];
    const float* density = (const float*)d_in[2];
    const float* sh      = (const float*)d_in[3];
    float* out           = (float*)d_out;

    const int R = in_sizes[0] / 3;      // 4096
    const int blocks = (R + 1) / 2;     // 2 rays (8 warps) per 256-thread block

    plenoxel_fwd_kernel<<<blocks, 256>>>(ro, rd, density, sh, out, R);
}